// round 3
// baseline (speedup 1.0000x reference)
#include <cuda_runtime.h>
#include <math.h>

#define T_SEQ 2048
#define E_DIM 1024
#define NH 8
#define LAMBDA_INIT 0.35550906759096927f

// ---------------- scratch (device globals; no runtime allocation) ----------------
__device__ float g_q[T_SEQ * E_DIM];
__device__ float g_k[T_SEQ * E_DIM];
__device__ float g_v[T_SEQ * E_DIM];
__device__ float g_attn[T_SEQ * E_DIM];
__device__ float g_lambda;

// ---------------- C[M,N] = A[M,K] * B[N,K]^T (both K-contiguous) ----------------
__global__ __launch_bounds__(256) void gemm_abt(const float* __restrict__ A,
                                                const float* __restrict__ B,
                                                float* __restrict__ C,
                                                int M, int N, int K) {
    __shared__ float sA[64][17];
    __shared__ float sB[64][17];
    const int bm = blockIdx.y * 64, bn = blockIdx.x * 64;
    const int tx = threadIdx.x & 15, ty = threadIdx.x >> 4;
    const int lr = threadIdx.x >> 2;          // 0..63
    const int lk = (threadIdx.x & 3) << 2;    // 0,4,8,12

    float acc[4][4] = {};
    for (int k0 = 0; k0 < K; k0 += 16) {
        float4 av = *(const float4*)&A[(size_t)(bm + lr) * K + k0 + lk];
        float4 bv = *(const float4*)&B[(size_t)(bn + lr) * K + k0 + lk];
        sA[lr][lk] = av.x; sA[lr][lk + 1] = av.y; sA[lr][lk + 2] = av.z; sA[lr][lk + 3] = av.w;
        sB[lr][lk] = bv.x; sB[lr][lk + 1] = bv.y; sB[lr][lk + 2] = bv.z; sB[lr][lk + 3] = bv.w;
        __syncthreads();
#pragma unroll
        for (int kk = 0; kk < 16; kk++) {
            float a[4], b[4];
#pragma unroll
            for (int i = 0; i < 4; i++) a[i] = sA[ty * 4 + i][kk];
#pragma unroll
            for (int j = 0; j < 4; j++) b[j] = sB[tx * 4 + j][kk];
#pragma unroll
            for (int i = 0; i < 4; i++)
#pragma unroll
                for (int j = 0; j < 4; j++) acc[i][j] += a[i] * b[j];
        }
        __syncthreads();
    }
#pragma unroll
    for (int i = 0; i < 4; i++) {
        float4 o = make_float4(acc[i][0], acc[i][1], acc[i][2], acc[i][3]);
        *(float4*)&C[(size_t)(bm + ty * 4 + i) * N + bn + tx * 4] = o;
    }
}

// ---------------- RoPE (xPos) on q (x scale, x D^-0.5) and k (x 1/scale) ----------------
// freqs: repeat-paired (dims 2i,2i+1 share inv_freq[i]); scale: concat-halved (index j -> sv[j%32])
__global__ void rope_kernel(float* __restrict__ q, float* __restrict__ k) {
    int t = blockIdx.x;             // 0..2047
    int p = threadIdx.x;            // 0..511
    int head = p >> 5;              // 0..15
    int i = p & 31;                 // pair index (dims 2i, 2i+1)

    // angle with double range reduction (robust under fast-math cosf/sinf)
    double inv = pow(10000.0, -(double)i / 32.0);
    double f = fmod((double)t * inv, 6.283185307179586);
    float cf = cosf((float)f), sf = sinf((float)f);

    float power = ((float)t - 1024.0f) / 512.0f;
    int je = (2 * i) & 31, jo = (2 * i + 1) & 31;
    float sv_e = (2.0f * je + 25.6f) / 89.6f;
    float sv_o = (2.0f * jo + 25.6f) / 89.6f;
    float se = powf(sv_e, power), so = powf(sv_o, power);

    size_t base = (size_t)t * E_DIM + head * 64 + 2 * i;
    float a = q[base], b = q[base + 1];
    q[base]     = (a * cf - b * sf) * se * 0.125f;   // * D^{-1/2}
    q[base + 1] = (b * cf + a * sf) * so * 0.125f;
    float ka = k[base], kb = k[base + 1];
    k[base]     = (ka * cf - kb * sf) / se;
    k[base + 1] = (kb * cf + ka * sf) / so;
}

// ---------------- lambda scalar ----------------
__global__ void lambda_kernel(const float* __restrict__ lq1, const float* __restrict__ lk1,
                              const float* __restrict__ lq2, const float* __restrict__ lk2) {
    __shared__ float s1[64], s2[64];
    int t = threadIdx.x;
    s1[t] = lq1[t] * lk1[t];
    s2[t] = lq2[t] * lk2[t];
    __syncthreads();
    if (t == 0) {
        float a = 0.f, b = 0.f;
        for (int j = 0; j < 64; j++) { a += s1[j]; b += s2[j]; }
        g_lambda = expf(a) - expf(b) + LAMBDA_INIT;
    }
}

// ---------------- fused differential flash attention ----------------
// grid (32 q-blocks, 8 heads), 256 threads, dynamic smem
// Per head h: stream0 = logical head 2h, stream1 = 2h+1; V = head h (128 dims)
#define SMEM_ATTN_FLOATS (2 * 64 * 65 + 2 * 64 * 64 + 64 * 128 + 64 * 65)
#define SMEM_ATTN_BYTES (SMEM_ATTN_FLOATS * 4)

__global__ __launch_bounds__(256) void diff_attn_kernel(const float* __restrict__ q,
                                                        const float* __restrict__ k,
                                                        const float* __restrict__ v,
                                                        float* __restrict__ attn_out) {
    extern __shared__ float sm[];
    float* sQ1 = sm;                     // 64 x 65
    float* sQ2 = sQ1 + 64 * 65;          // 64 x 65
    float* sK1 = sQ2 + 64 * 65;          // transposed [d][s] 64 x 64
    float* sK2 = sK1 + 64 * 64;
    float* sV  = sK2 + 64 * 64;          // [s][c] 64 x 128
    float* sP  = sV + 64 * 128;          // 64 x 65

    const int bq = blockIdx.x;   // 0..31
    const int h  = blockIdx.y;   // 0..7
    const int tid = threadIdx.x;
    const int tx = tid & 15, ty = tid >> 4;
    const int q0 = bq * 64;

    // load resident Q tiles (both streams)
    for (int idx = tid; idx < 64 * 64; idx += 256) {
        int r = idx >> 6, d = idx & 63;
        sQ1[r * 65 + d] = q[(size_t)(q0 + r) * E_DIM + (2 * h) * 64 + d];
        sQ2[r * 65 + d] = q[(size_t)(q0 + r) * E_DIM + (2 * h + 1) * 64 + d];
    }

    float m_[2][4], l_[2][4], O_[2][4][8];
#pragma unroll
    for (int st = 0; st < 2; st++)
#pragma unroll
        for (int i = 0; i < 4; i++) {
            m_[st][i] = -INFINITY; l_[st][i] = 0.f;
#pragma unroll
            for (int c = 0; c < 8; c++) O_[st][i][c] = 0.f;
        }

    for (int sb = 0; sb < 32; sb++) {
        const int s0 = sb * 64;
        // load K (transposed) and V tiles
        for (int idx = tid; idx < 64 * 64; idx += 256) {
            int r = idx >> 6, d = idx & 63;
            sK1[d * 64 + r] = k[(size_t)(s0 + r) * E_DIM + (2 * h) * 64 + d];
            sK2[d * 64 + r] = k[(size_t)(s0 + r) * E_DIM + (2 * h + 1) * 64 + d];
        }
        for (int idx = tid; idx < 64 * 128; idx += 256) {
            int r = idx >> 7, c = idx & 127;
            sV[r * 128 + c] = v[(size_t)(s0 + r) * E_DIM + h * 128 + c];
        }
        __syncthreads();

#pragma unroll
        for (int st = 0; st < 2; st++) {
            const float* sQ = st ? sQ2 : sQ1;
            const float* sK = st ? sK2 : sK1;

            // S tile: 4x4 per thread (rows ty*4.., cols tx*4..)
            float acc[4][4] = {};
#pragma unroll 16
            for (int kk = 0; kk < 64; kk++) {
                float4 b4 = *(const float4*)&sK[kk * 64 + tx * 4];
                float a0 = sQ[(ty * 4 + 0) * 65 + kk];
                float a1 = sQ[(ty * 4 + 1) * 65 + kk];
                float a2 = sQ[(ty * 4 + 2) * 65 + kk];
                float a3 = sQ[(ty * 4 + 3) * 65 + kk];
                acc[0][0] += a0 * b4.x; acc[0][1] += a0 * b4.y; acc[0][2] += a0 * b4.z; acc[0][3] += a0 * b4.w;
                acc[1][0] += a1 * b4.x; acc[1][1] += a1 * b4.y; acc[1][2] += a1 * b4.z; acc[1][3] += a1 * b4.w;
                acc[2][0] += a2 * b4.x; acc[2][1] += a2 * b4.y; acc[2][2] += a2 * b4.z; acc[2][3] += a2 * b4.w;
                acc[3][0] += a3 * b4.x; acc[3][1] += a3 * b4.y; acc[3][2] += a3 * b4.z; acc[3][3] += a3 * b4.w;
            }

            // online softmax update + write P
#pragma unroll
            for (int i = 0; i < 4; i++) {
                float rmax = fmaxf(fmaxf(acc[i][0], acc[i][1]), fmaxf(acc[i][2], acc[i][3]));
#pragma unroll
                for (int off = 8; off >= 1; off >>= 1)
                    rmax = fmaxf(rmax, __shfl_xor_sync(0xffffffffu, rmax, off));
                float mnew = fmaxf(m_[st][i], rmax);
                float alpha = __expf(m_[st][i] - mnew);
                m_[st][i] = mnew;
                float p0 = __expf(acc[i][0] - mnew);
                float p1 = __expf(acc[i][1] - mnew);
                float p2 = __expf(acc[i][2] - mnew);
                float p3 = __expf(acc[i][3] - mnew);
                float rs = p0 + p1 + p2 + p3;
#pragma unroll
                for (int off = 8; off >= 1; off >>= 1)
                    rs += __shfl_xor_sync(0xffffffffu, rs, off);
                l_[st][i] = l_[st][i] * alpha + rs;
#pragma unroll
                for (int c = 0; c < 8; c++) O_[st][i][c] *= alpha;
                float* pr = &sP[(ty * 4 + i) * 65 + tx * 4];
                pr[0] = p0; pr[1] = p1; pr[2] = p2; pr[3] = p3;
            }
            __syncthreads();

            // O += P * V  (rows ty*4.., cols tx*8..)
#pragma unroll 8
            for (int s = 0; s < 64; s++) {
                float4 v0 = *(const float4*)&sV[s * 128 + tx * 8];
                float4 v1 = *(const float4*)&sV[s * 128 + tx * 8 + 4];
#pragma unroll
                for (int i = 0; i < 4; i++) {
                    float p = sP[(ty * 4 + i) * 65 + s];
                    O_[st][i][0] += p * v0.x; O_[st][i][1] += p * v0.y;
                    O_[st][i][2] += p * v0.z; O_[st][i][3] += p * v0.w;
                    O_[st][i][4] += p * v1.x; O_[st][i][5] += p * v1.y;
                    O_[st][i][6] += p * v1.z; O_[st][i][7] += p * v1.w;
                }
            }
            __syncthreads();
        }
    }

    // epilogue: diff, RMS-norm over 128 dims, scale, write
    const float lam = g_lambda;
#pragma unroll
    for (int i = 0; i < 4; i++) {
        float inv1 = 1.0f / l_[0][i];
        float inv2 = 1.0f / l_[1][i];
        float o[8];
        float ss = 0.f;
#pragma unroll
        for (int c = 0; c < 8; c++) {
            o[c] = O_[0][i][c] * inv1 - lam * (O_[1][i][c] * inv2);
            ss += o[c] * o[c];
        }
#pragma unroll
        for (int off = 8; off >= 1; off >>= 1)
            ss += __shfl_xor_sync(0xffffffffu, ss, off);
        float rms = rsqrtf(ss * (1.0f / 128.0f) + 1e-5f);
        float g = rms * (1.0f - LAMBDA_INIT);
        int r = q0 + ty * 4 + i;
        float* dst = &attn_out[(size_t)r * E_DIM + h * 128 + tx * 8];
        float4 w0 = make_float4(o[0] * g, o[1] * g, o[2] * g, o[3] * g);
        float4 w1 = make_float4(o[4] * g, o[5] * g, o[6] * g, o[7] * g);
        *(float4*)&dst[0] = w0;
        *(float4*)&dst[4] = w1;
    }
}

// ---------------- launch ----------------
extern "C" void kernel_launch(void* const* d_in, const int* in_sizes, int n_in,
                              void* d_out, int out_size) {
    const float* x   = (const float*)d_in[0];
    const float* Wq  = (const float*)d_in[1];
    const float* Wk  = (const float*)d_in[2];
    const float* Wv  = (const float*)d_in[3];
    const float* Wo  = (const float*)d_in[4];
    const float* lq1 = (const float*)d_in[5];
    const float* lk1 = (const float*)d_in[6];
    const float* lq2 = (const float*)d_in[7];
    const float* lk2 = (const float*)d_in[8];
    float* out = (float*)d_out;

    float *pq, *pk, *pv, *pattn;
    cudaGetSymbolAddress((void**)&pq, g_q);
    cudaGetSymbolAddress((void**)&pk, g_k);
    cudaGetSymbolAddress((void**)&pv, g_v);
    cudaGetSymbolAddress((void**)&pattn, g_attn);

    dim3 ggrid(E_DIM / 64, T_SEQ / 64);
    gemm_abt<<<ggrid, 256>>>(x, Wq, pq, T_SEQ, E_DIM, E_DIM);
    gemm_abt<<<ggrid, 256>>>(x, Wk, pk, T_SEQ, E_DIM, E_DIM);
    gemm_abt<<<ggrid, 256>>>(x, Wv, pv, T_SEQ, E_DIM, E_DIM);

    rope_kernel<<<T_SEQ, 512>>>(pq, pk);
    lambda_kernel<<<1, 64>>>(lq1, lk1, lq2, lk2);

    cudaFuncSetAttribute(diff_attn_kernel, cudaFuncAttributeMaxDynamicSharedMemorySize,
                         SMEM_ATTN_BYTES);
    diff_attn_kernel<<<dim3(T_SEQ / 64, NH), 256, SMEM_ATTN_BYTES>>>(pq, pk, pv, pattn);

    gemm_abt<<<ggrid, 256>>>(pattn, Wo, out, T_SEQ, E_DIM, E_DIM);
}

// round 10
// speedup vs baseline: 1.4206x; 1.4206x over previous
#include <cuda_runtime.h>
#include <cuda_bf16.h>
#include <cstdint>
#include <math.h>

#define T_SEQ 2048
#define E_DIM 1024
#define NH 8
#define LAMBDA_INIT 0.35550906759096927f

// ---------------- scratch (device globals; no runtime allocation) ----------------
__device__ float g_q[T_SEQ * E_DIM];
__device__ float g_k[T_SEQ * E_DIM];
__device__ float g_v[T_SEQ * E_DIM];
__device__ float g_attn[T_SEQ * E_DIM];
__device__ float g_lambda;
__device__ float g_rope[T_SEQ * 32 * 4];

__device__ __nv_bfloat16 g_xh[T_SEQ * E_DIM], g_xl[T_SEQ * E_DIM];
__device__ __nv_bfloat16 g_ah[T_SEQ * E_DIM], g_al[T_SEQ * E_DIM];
__device__ __nv_bfloat16 g_wqh[E_DIM * E_DIM], g_wql[E_DIM * E_DIM];
__device__ __nv_bfloat16 g_wkh[E_DIM * E_DIM], g_wkl[E_DIM * E_DIM];
__device__ __nv_bfloat16 g_wvh[E_DIM * E_DIM], g_wvl[E_DIM * E_DIM];
__device__ __nv_bfloat16 g_woh[E_DIM * E_DIM], g_wol[E_DIM * E_DIM];

// ---------------- warp-MMA helpers (baseline PTX, works at sm_103 non-a) ----------------
__device__ __forceinline__ uint32_t smem_u32(const void* p) {
    uint32_t a;
    asm("{ .reg .u64 t; cvta.to.shared.u64 t, %1; cvt.u32.u64 %0, t; }" : "=r"(a) : "l"(p));
    return a;
}
__device__ __forceinline__ void ldsm4(uint32_t* r, uint32_t addr) {
    asm volatile("ldmatrix.sync.aligned.m8n8.x4.shared.b16 {%0,%1,%2,%3}, [%4];"
                 : "=r"(r[0]), "=r"(r[1]), "=r"(r[2]), "=r"(r[3]) : "r"(addr));
}
__device__ __forceinline__ void mma16816(float* d, const uint32_t* a, const uint32_t* b) {
    asm volatile("mma.sync.aligned.m16n8k16.row.col.f32.bf16.bf16.f32 "
                 "{%0,%1,%2,%3}, {%4,%5,%6,%7}, {%8,%9}, {%0,%1,%2,%3};"
                 : "+f"(d[0]), "+f"(d[1]), "+f"(d[2]), "+f"(d[3])
                 : "r"(a[0]), "r"(a[1]), "r"(a[2]), "r"(a[3]), "r"(b[0]), "r"(b[1]));
}

// ---------------- split-bf16 conversion ----------------
__global__ void cvt_split(const float* __restrict__ in, __nv_bfloat16* __restrict__ hi,
                          __nv_bfloat16* __restrict__ lo, int n) {
    int i = blockIdx.x * 256 + threadIdx.x;
    if (i < n) {
        float v = in[i];
        __nv_bfloat16 h = __float2bfloat16(v);
        hi[i] = h;
        lo[i] = __float2bfloat16(v - __bfloat162float(h));
    }
}

// ---------------- HMMA GEMM: C[M,N] = A[M,K] * B[N,K]^T, split-bf16 3-term ----------------
// CTA 128x128, 8 warps (4M x 2N), warp tile 32x64, K-chunk 32, reg-prefetch pipeline.
// smem rows: 32 bf16 data + 8 pad = 40 elems (80 B) -> ldmatrix bank-conflict-free.
#define SROW 40

__global__ __launch_bounds__(256) void gemm_hmma(const __nv_bfloat16* __restrict__ Ah,
                                                 const __nv_bfloat16* __restrict__ Al,
                                                 const __nv_bfloat16* __restrict__ Bh,
                                                 const __nv_bfloat16* __restrict__ Bl,
                                                 float* __restrict__ C,
                                                 int M, int N, int K) {
    __shared__ __align__(16) __nv_bfloat16 sAh[128 * SROW];
    __shared__ __align__(16) __nv_bfloat16 sAl[128 * SROW];
    __shared__ __align__(16) __nv_bfloat16 sBh[128 * SROW];
    __shared__ __align__(16) __nv_bfloat16 sBl[128 * SROW];

    const int tid = threadIdx.x;
    const int lane = tid & 31, wid = tid >> 5;
    const int wm = wid & 3, wn = wid >> 2;           // 4 M-warps x 2 N-warps
    const int m0 = blockIdx.y * 128, n0 = blockIdx.x * 128;

    const uint32_t uAh = smem_u32(sAh), uAl = smem_u32(sAl);
    const uint32_t uBh = smem_u32(sBh), uBl = smem_u32(sBl);

    float acc[2][8][4];
#pragma unroll
    for (int mt = 0; mt < 2; mt++)
#pragma unroll
        for (int nt = 0; nt < 8; nt++)
#pragma unroll
            for (int i = 0; i < 4; i++) acc[mt][nt][i] = 0.f;

    // per-thread gmem/smem copy coordinates: 512 uint4 per tile, 2 per thread
    int rowA[2], qA[2];
#pragma unroll
    for (int j = 0; j < 2; j++) {
        int u = tid + j * 256;
        rowA[j] = u >> 2;
        qA[j] = u & 3;
    }

    uint4 pAh[2], pAl[2], pBh[2], pBl[2];
#pragma unroll
    for (int j = 0; j < 2; j++) {
        size_t ga = (size_t)(m0 + rowA[j]) * K + qA[j] * 8;
        size_t gb = (size_t)(n0 + rowA[j]) * K + qA[j] * 8;
        pAh[j] = *(const uint4*)&Ah[ga];
        pAl[j] = *(const uint4*)&Al[ga];
        pBh[j] = *(const uint4*)&Bh[gb];
        pBl[j] = *(const uint4*)&Bl[gb];
    }

    const int nchunk = K >> 5;
    for (int c = 0; c < nchunk; c++) {
        // stage prefetched chunk into smem
#pragma unroll
        for (int j = 0; j < 2; j++) {
            int so = rowA[j] * SROW + qA[j] * 8;
            *(uint4*)&sAh[so] = pAh[j];
            *(uint4*)&sAl[so] = pAl[j];
            *(uint4*)&sBh[so] = pBh[j];
            *(uint4*)&sBl[so] = pBl[j];
        }
        __syncthreads();

        // prefetch next chunk into registers
        if (c + 1 < nchunk) {
            int k0 = (c + 1) << 5;
#pragma unroll
            for (int j = 0; j < 2; j++) {
                size_t ga = (size_t)(m0 + rowA[j]) * K + k0 + qA[j] * 8;
                size_t gb = (size_t)(n0 + rowA[j]) * K + k0 + qA[j] * 8;
                pAh[j] = *(const uint4*)&Ah[ga];
                pAl[j] = *(const uint4*)&Al[ga];
                pBh[j] = *(const uint4*)&Bh[gb];
                pBl[j] = *(const uint4*)&Bl[gb];
            }
        }

        // compute: 2 K16 steps
#pragma unroll
        for (int ks = 0; ks < 2; ks++) {
            uint32_t aH[2][4], aL[2][4], bH[16], bL[16];
#pragma unroll
            for (int mt = 0; mt < 2; mt++) {
                uint32_t off = (uint32_t)(wm * 32 + mt * 16 + (lane & 15)) * (SROW * 2)
                               + ks * 32 + ((lane >> 4) * 16);
                ldsm4(aH[mt], uAh + off);
                ldsm4(aL[mt], uAl + off);
            }
            {
                int quarter = lane >> 3, wi = lane & 7;
#pragma unroll
                for (int p = 0; p < 4; p++) {
                    uint32_t off = (uint32_t)(wn * 64 + p * 16 + (quarter >> 1) * 8 + wi) * (SROW * 2)
                                   + ks * 32 + ((quarter & 1) * 16);
                    ldsm4(&bH[p * 4], uBh + off);
                    ldsm4(&bL[p * 4], uBl + off);
                }
            }
#pragma unroll
            for (int mt = 0; mt < 2; mt++)
#pragma unroll
                for (int nt = 0; nt < 8; nt++) {
                    mma16816(acc[mt][nt], aH[mt], &bH[nt * 2]);
                    mma16816(acc[mt][nt], aH[mt], &bL[nt * 2]);
                    mma16816(acc[mt][nt], aL[mt], &bH[nt * 2]);
                }
        }
        __syncthreads();
    }

    // epilogue: C fragment layout -> global
#pragma unroll
    for (int mt = 0; mt < 2; mt++) {
        int row = m0 + wm * 32 + mt * 16 + (lane >> 2);
#pragma unroll
        for (int nt = 0; nt < 8; nt++) {
            int col = n0 + wn * 64 + nt * 8 + (lane & 3) * 2;
            float2 v0 = make_float2(acc[mt][nt][0], acc[mt][nt][1]);
            float2 v1 = make_float2(acc[mt][nt][2], acc[mt][nt][3]);
            *(float2*)&C[(size_t)row * N + col] = v0;
            *(float2*)&C[(size_t)(row + 8) * N + col] = v1;
        }
    }
}

// ---------------- RoPE tables (tiny fp64 kernel) ----------------
__global__ void rope_tables(float* __restrict__ tab) {
    int t = blockIdx.x;      // 0..2047
    int i = threadIdx.x;     // 0..31 (pair index)
    double inv = pow(10000.0, -(double)i / 32.0);
    double f = fmod((double)t * inv, 6.283185307179586);
    float cf = (float)cos(f), sf = (float)sin(f);
    float power = ((float)t - 1024.0f) / 512.0f;
    int je = (2 * i) & 31, jo = (2 * i + 1) & 31;
    float sv_e = (2.0f * je + 25.6f) / 89.6f;
    float sv_o = (2.0f * jo + 25.6f) / 89.6f;
    float se = powf(sv_e, power), so = powf(sv_o, power);
    int idx = (t * 32 + i) * 4;
    tab[idx] = cf; tab[idx + 1] = sf; tab[idx + 2] = se; tab[idx + 3] = so;
}

// ---------------- RoPE apply (pure float, table lookup) ----------------
__global__ void rope_apply(float* __restrict__ q, float* __restrict__ k,
                           const float* __restrict__ tab) {
    int t = blockIdx.x;
    int p = threadIdx.x;        // 0..511
    int head = p >> 5;
    int i = p & 31;
    float4 tv = *(const float4*)&tab[(t * 32 + i) * 4];
    float cf = tv.x, sf = tv.y, se = tv.z, so = tv.w;

    size_t base = (size_t)t * E_DIM + head * 64 + 2 * i;
    float a = q[base], b = q[base + 1];
    q[base]     = (a * cf - b * sf) * se * 0.125f;
    q[base + 1] = (b * cf + a * sf) * so * 0.125f;
    float ka = k[base], kb = k[base + 1];
    k[base]     = (ka * cf - kb * sf) / se;
    k[base + 1] = (kb * cf + ka * sf) / so;
}

// ---------------- lambda scalar ----------------
__global__ void lambda_kernel(const float* __restrict__ lq1, const float* __restrict__ lk1,
                              const float* __restrict__ lq2, const float* __restrict__ lk2) {
    __shared__ float s1[64], s2[64];
    int t = threadIdx.x;
    s1[t] = lq1[t] * lk1[t];
    s2[t] = lq2[t] * lk2[t];
    __syncthreads();
    if (t == 0) {
        float a = 0.f, b = 0.f;
        for (int j = 0; j < 64; j++) { a += s1[j]; b += s2[j]; }
        g_lambda = expf(a) - expf(b) + LAMBDA_INIT;
    }
}

// ---------------- fused differential flash attention (fp32) ----------------
#define SMEM_ATTN_FLOATS (2 * 64 * 65 + 2 * 64 * 64 + 64 * 128 + 64 * 65)
#define SMEM_ATTN_BYTES (SMEM_ATTN_FLOATS * 4)

__global__ __launch_bounds__(256) void diff_attn_kernel(const float* __restrict__ q,
                                                        const float* __restrict__ k,
                                                        const float* __restrict__ v,
                                                        float* __restrict__ attn_out) {
    extern __shared__ float sm[];
    float* sQ1 = sm;
    float* sQ2 = sQ1 + 64 * 65;
    float* sK1 = sQ2 + 64 * 65;
    float* sK2 = sK1 + 64 * 64;
    float* sV  = sK2 + 64 * 64;
    float* sP  = sV + 64 * 128;

    const int bq = blockIdx.x;
    const int h  = blockIdx.y;
    const int tid = threadIdx.x;
    const int tx = tid & 15, ty = tid >> 4;
    const int q0 = bq * 64;

    for (int idx = tid; idx < 64 * 64; idx += 256) {
        int r = idx >> 6, d = idx & 63;
        sQ1[r * 65 + d] = q[(size_t)(q0 + r) * E_DIM + (2 * h) * 64 + d];
        sQ2[r * 65 + d] = q[(size_t)(q0 + r) * E_DIM + (2 * h + 1) * 64 + d];
    }

    float m_[2][4], l_[2][4], O_[2][4][8];
#pragma unroll
    for (int st = 0; st < 2; st++)
#pragma unroll
        for (int i = 0; i < 4; i++) {
            m_[st][i] = -INFINITY; l_[st][i] = 0.f;
#pragma unroll
            for (int c = 0; c < 8; c++) O_[st][i][c] = 0.f;
        }

    for (int sb = 0; sb < 32; sb++) {
        const int s0 = sb * 64;
        for (int idx = tid; idx < 64 * 64; idx += 256) {
            int r = idx >> 6, d = idx & 63;
            sK1[d * 64 + r] = k[(size_t)(s0 + r) * E_DIM + (2 * h) * 64 + d];
            sK2[d * 64 + r] = k[(size_t)(s0 + r) * E_DIM + (2 * h + 1) * 64 + d];
        }
        for (int idx = tid; idx < 64 * 128; idx += 256) {
            int r = idx >> 7, c = idx & 127;
            sV[r * 128 + c] = v[(size_t)(s0 + r) * E_DIM + h * 128 + c];
        }
        __syncthreads();

#pragma unroll
        for (int st = 0; st < 2; st++) {
            const float* sQ = st ? sQ2 : sQ1;
            const float* sK = st ? sK2 : sK1;

            float acc[4][4] = {};
#pragma unroll 16
            for (int kk = 0; kk < 64; kk++) {
                float4 b4 = *(const float4*)&sK[kk * 64 + tx * 4];
                float a0 = sQ[(ty * 4 + 0) * 65 + kk];
                float a1 = sQ[(ty * 4 + 1) * 65 + kk];
                float a2 = sQ[(ty * 4 + 2) * 65 + kk];
                float a3 = sQ[(ty * 4 + 3) * 65 + kk];
                acc[0][0] += a0 * b4.x; acc[0][1] += a0 * b4.y; acc[0][2] += a0 * b4.z; acc[0][3] += a0 * b4.w;
                acc[1][0] += a1 * b4.x; acc[1][1] += a1 * b4.y; acc[1][2] += a1 * b4.z; acc[1][3] += a1 * b4.w;
                acc[2][0] += a2 * b4.x; acc[2][1] += a2 * b4.y; acc[2][2] += a2 * b4.z; acc[2][3] += a2 * b4.w;
                acc[3][0] += a3 * b4.x; acc[3][1] += a3 * b4.y; acc[3][2] += a3 * b4.z; acc[3][3] += a3 * b4.w;
            }

#pragma unroll
            for (int i = 0; i < 4; i++) {
                float rmax = fmaxf(fmaxf(acc[i][0], acc[i][1]), fmaxf(acc[i][2], acc[i][3]));
#pragma unroll
                for (int off = 8; off >= 1; off >>= 1)
                    rmax = fmaxf(rmax, __shfl_xor_sync(0xffffffffu, rmax, off));
                float mnew = fmaxf(m_[st][i], rmax);
                float alpha = __expf(m_[st][i] - mnew);
                m_[st][i] = mnew;
                float p0 = __expf(acc[i][0] - mnew);
                float p1 = __expf(acc[i][1] - mnew);
                float p2 = __expf(acc[i][2] - mnew);
                float p3 = __expf(acc[i][3] - mnew);
                float rs = p0 + p1 + p2 + p3;
#pragma unroll
                for (int off = 8; off >= 1; off >>= 1)
                    rs += __shfl_xor_sync(0xffffffffu, rs, off);
                l_[st][i] = l_[st][i] * alpha + rs;
#pragma unroll
                for (int c = 0; c < 8; c++) O_[st][i][c] *= alpha;
                float* pr = &sP[(ty * 4 + i) * 65 + tx * 4];
                pr[0] = p0; pr[1] = p1; pr[2] = p2; pr[3] = p3;
            }
            __syncthreads();

#pragma unroll 8
            for (int s = 0; s < 64; s++) {
                float4 v0 = *(const float4*)&sV[s * 128 + tx * 8];
                float4 v1 = *(const float4*)&sV[s * 128 + tx * 8 + 4];
#pragma unroll
                for (int i = 0; i < 4; i++) {
                    float p = sP[(ty * 4 + i) * 65 + s];
                    O_[st][i][0] += p * v0.x; O_[st][i][1] += p * v0.y;
                    O_[st][i][2] += p * v0.z; O_[st][i][3] += p * v0.w;
                    O_[st][i][4] += p * v1.x; O_[st][i][5] += p * v1.y;
                    O_[st][i][6] += p * v1.z; O_[st][i][7] += p * v1.w;
                }
            }
            __syncthreads();
        }
    }

    const float lam = g_lambda;
#pragma unroll
    for (int i = 0; i < 4; i++) {
        float inv1 = 1.0f / l_[0][i];
        float inv2 = 1.0f / l_[1][i];
        float o[8];
        float ss = 0.f;
#pragma unroll
        for (int c = 0; c < 8; c++) {
            o[c] = O_[0][i][c] * inv1 - lam * (O_[1][i][c] * inv2);
            ss += o[c] * o[c];
        }
#pragma unroll
        for (int off = 8; off >= 1; off >>= 1)
            ss += __shfl_xor_sync(0xffffffffu, ss, off);
        float rms = rsqrtf(ss * (1.0f / 128.0f) + 1e-5f);
        float g = rms * (1.0f - LAMBDA_INIT);
        int r = q0 + ty * 4 + i;
        float* dst = &attn_out[(size_t)r * E_DIM + h * 128 + tx * 8];
        float4 w0 = make_float4(o[0] * g, o[1] * g, o[2] * g, o[3] * g);
        float4 w1 = make_float4(o[4] * g, o[5] * g, o[6] * g, o[7] * g);
        *(float4*)&dst[0] = w0;
        *(float4*)&dst[4] = w1;
    }
}

// ---------------- launch ----------------
extern "C" void kernel_launch(void* const* d_in, const int* in_sizes, int n_in,
                              void* d_out, int out_size) {
    const float* x   = (const float*)d_in[0];
    const float* Wq  = (const float*)d_in[1];
    const float* Wk  = (const float*)d_in[2];
    const float* Wv  = (const float*)d_in[3];
    const float* Wo  = (const float*)d_in[4];
    const float* lq1 = (const float*)d_in[5];
    const float* lk1 = (const float*)d_in[6];
    const float* lq2 = (const float*)d_in[7];
    const float* lk2 = (const float*)d_in[8];
    float* out = (float*)d_out;

    float *pq, *pk, *pv, *pattn, *ptab;
    cudaGetSymbolAddress((void**)&pq, g_q);
    cudaGetSymbolAddress((void**)&pk, g_k);
    cudaGetSymbolAddress((void**)&pv, g_v);
    cudaGetSymbolAddress((void**)&pattn, g_attn);
    cudaGetSymbolAddress((void**)&ptab, g_rope);

    __nv_bfloat16 *xh, *xl, *ah, *al, *wqh, *wql, *wkh, *wkl, *wvh, *wvl, *woh, *wol;
    cudaGetSymbolAddress((void**)&xh, g_xh);   cudaGetSymbolAddress((void**)&xl, g_xl);
    cudaGetSymbolAddress((void**)&ah, g_ah);   cudaGetSymbolAddress((void**)&al, g_al);
    cudaGetSymbolAddress((void**)&wqh, g_wqh); cudaGetSymbolAddress((void**)&wql, g_wql);
    cudaGetSymbolAddress((void**)&wkh, g_wkh); cudaGetSymbolAddress((void**)&wkl, g_wkl);
    cudaGetSymbolAddress((void**)&wvh, g_wvh); cudaGetSymbolAddress((void**)&wvl, g_wvl);
    cudaGetSymbolAddress((void**)&woh, g_woh); cudaGetSymbolAddress((void**)&wol, g_wol);

    cudaFuncSetAttribute(diff_attn_kernel, cudaFuncAttributeMaxDynamicSharedMemorySize,
                         SMEM_ATTN_BYTES);

    const int nX = T_SEQ * E_DIM;   // 2M
    const int nW = E_DIM * E_DIM;   // 1M
    cvt_split<<<(nX + 255) / 256, 256>>>(x, xh, xl, nX);
    cvt_split<<<(nW + 255) / 256, 256>>>(Wq, wqh, wql, nW);
    cvt_split<<<(nW + 255) / 256, 256>>>(Wk, wkh, wkl, nW);
    cvt_split<<<(nW + 255) / 256, 256>>>(Wv, wvh, wvl, nW);
    cvt_split<<<(nW + 255) / 256, 256>>>(Wo, woh, wol, nW);

    rope_tables<<<T_SEQ, 32>>>(ptab);
    lambda_kernel<<<1, 64>>>(lq1, lk1, lq2, lk2);

    dim3 tgrid(E_DIM / 128, T_SEQ / 128);   // (8, 16)
    gemm_hmma<<<tgrid, 256>>>(xh, xl, wqh, wql, pq, T_SEQ, E_DIM, E_DIM);
    gemm_hmma<<<tgrid, 256>>>(xh, xl, wkh, wkl, pk, T_SEQ, E_DIM, E_DIM);
    gemm_hmma<<<tgrid, 256>>>(xh, xl, wvh, wvl, pv, T_SEQ, E_DIM, E_DIM);

    rope_apply<<<T_SEQ, 512>>>(pq, pk, ptab);

    diff_attn_kernel<<<dim3(T_SEQ / 64, NH), 256, SMEM_ATTN_BYTES>>>(pq, pk, pv, pattn);

    cvt_split<<<(nX + 255) / 256, 256>>>(pattn, ah, al, nX);
    gemm_hmma<<<tgrid, 256>>>(ah, al, woh, wol, out, T_SEQ, E_DIM, E_DIM);
}

// round 11
// speedup vs baseline: 3.7972x; 2.6729x over previous
#include <cuda_runtime.h>
#include <cuda_bf16.h>
#include <cstdint>
#include <math.h>

#define T_SEQ 2048
#define E_DIM 1024
#define NH 8
#define LAMBDA_INIT 0.35550906759096927f

// ---------------- scratch (device globals; no runtime allocation) ----------------
__device__ float g_q[T_SEQ * E_DIM];
__device__ float g_k[T_SEQ * E_DIM];
__device__ float g_v[T_SEQ * E_DIM];
__device__ float g_lambda;
__device__ float g_rope[T_SEQ * 32 * 4];

__device__ __nv_bfloat16 g_xh[T_SEQ * E_DIM], g_xl[T_SEQ * E_DIM];
__device__ __nv_bfloat16 g_ah[T_SEQ * E_DIM], g_al[T_SEQ * E_DIM];
__device__ __nv_bfloat16 g_qbh[T_SEQ * E_DIM], g_qbl[T_SEQ * E_DIM];
__device__ __nv_bfloat16 g_kbh[T_SEQ * E_DIM], g_kbl[T_SEQ * E_DIM];
__device__ __nv_bfloat16 g_vbh[T_SEQ * E_DIM], g_vbl[T_SEQ * E_DIM];
__device__ __nv_bfloat16 g_wqh[E_DIM * E_DIM], g_wql[E_DIM * E_DIM];
__device__ __nv_bfloat16 g_wkh[E_DIM * E_DIM], g_wkl[E_DIM * E_DIM];
__device__ __nv_bfloat16 g_wvh[E_DIM * E_DIM], g_wvl[E_DIM * E_DIM];
__device__ __nv_bfloat16 g_woh[E_DIM * E_DIM], g_wol[E_DIM * E_DIM];

// ---------------- warp-MMA helpers (baseline PTX, works at sm_103 non-a) ----------------
__device__ __forceinline__ uint32_t smem_u32(const void* p) {
    uint32_t a;
    asm("{ .reg .u64 t; cvta.to.shared.u64 t, %1; cvt.u32.u64 %0, t; }" : "=r"(a) : "l"(p));
    return a;
}
__device__ __forceinline__ void ldsm4(uint32_t* r, uint32_t addr) {
    asm volatile("ldmatrix.sync.aligned.m8n8.x4.shared.b16 {%0,%1,%2,%3}, [%4];"
                 : "=r"(r[0]), "=r"(r[1]), "=r"(r[2]), "=r"(r[3]) : "r"(addr));
}
__device__ __forceinline__ void ldsm4t(uint32_t* r, uint32_t addr) {
    asm volatile("ldmatrix.sync.aligned.m8n8.x4.trans.shared.b16 {%0,%1,%2,%3}, [%4];"
                 : "=r"(r[0]), "=r"(r[1]), "=r"(r[2]), "=r"(r[3]) : "r"(addr));
}
__device__ __forceinline__ void mma16816(float* d, const uint32_t* a, const uint32_t* b) {
    asm volatile("mma.sync.aligned.m16n8k16.row.col.f32.bf16.bf16.f32 "
                 "{%0,%1,%2,%3}, {%4,%5,%6,%7}, {%8,%9}, {%0,%1,%2,%3};"
                 : "+f"(d[0]), "+f"(d[1]), "+f"(d[2]), "+f"(d[3])
                 : "r"(a[0]), "r"(a[1]), "r"(a[2]), "r"(a[3]), "r"(b[0]), "r"(b[1]));
}

// ---------------- split-bf16 conversion ----------------
__global__ void cvt_split(const float* __restrict__ in, __nv_bfloat16* __restrict__ hi,
                          __nv_bfloat16* __restrict__ lo, int n) {
    int i = blockIdx.x * 256 + threadIdx.x;
    if (i < n) {
        float v = in[i];
        __nv_bfloat16 h = __float2bfloat16(v);
        hi[i] = h;
        lo[i] = __float2bfloat16(v - __bfloat162float(h));
    }
}

// ---------------- HMMA GEMM: C[M,N] = A[M,K] * B[N,K]^T, split-bf16 3-term ----------------
#define SROW 40

__global__ __launch_bounds__(256) void gemm_hmma(const __nv_bfloat16* __restrict__ Ah,
                                                 const __nv_bfloat16* __restrict__ Al,
                                                 const __nv_bfloat16* __restrict__ Bh,
                                                 const __nv_bfloat16* __restrict__ Bl,
                                                 float* __restrict__ C,
                                                 int M, int N, int K) {
    __shared__ __align__(16) __nv_bfloat16 sAh[128 * SROW];
    __shared__ __align__(16) __nv_bfloat16 sAl[128 * SROW];
    __shared__ __align__(16) __nv_bfloat16 sBh[128 * SROW];
    __shared__ __align__(16) __nv_bfloat16 sBl[128 * SROW];

    const int tid = threadIdx.x;
    const int lane = tid & 31, wid = tid >> 5;
    const int wm = wid & 3, wn = wid >> 2;
    const int m0 = blockIdx.y * 128, n0 = blockIdx.x * 128;

    const uint32_t uAh = smem_u32(sAh), uAl = smem_u32(sAl);
    const uint32_t uBh = smem_u32(sBh), uBl = smem_u32(sBl);

    float acc[2][8][4];
#pragma unroll
    for (int mt = 0; mt < 2; mt++)
#pragma unroll
        for (int nt = 0; nt < 8; nt++)
#pragma unroll
            for (int i = 0; i < 4; i++) acc[mt][nt][i] = 0.f;

    int rowA[2], qA[2];
#pragma unroll
    for (int j = 0; j < 2; j++) {
        int u = tid + j * 256;
        rowA[j] = u >> 2;
        qA[j] = u & 3;
    }

    uint4 pAh[2], pAl[2], pBh[2], pBl[2];
#pragma unroll
    for (int j = 0; j < 2; j++) {
        size_t ga = (size_t)(m0 + rowA[j]) * K + qA[j] * 8;
        size_t gb = (size_t)(n0 + rowA[j]) * K + qA[j] * 8;
        pAh[j] = *(const uint4*)&Ah[ga];
        pAl[j] = *(const uint4*)&Al[ga];
        pBh[j] = *(const uint4*)&Bh[gb];
        pBl[j] = *(const uint4*)&Bl[gb];
    }

    const int nchunk = K >> 5;
    for (int c = 0; c < nchunk; c++) {
#pragma unroll
        for (int j = 0; j < 2; j++) {
            int so = rowA[j] * SROW + qA[j] * 8;
            *(uint4*)&sAh[so] = pAh[j];
            *(uint4*)&sAl[so] = pAl[j];
            *(uint4*)&sBh[so] = pBh[j];
            *(uint4*)&sBl[so] = pBl[j];
        }
        __syncthreads();

        if (c + 1 < nchunk) {
            int k0 = (c + 1) << 5;
#pragma unroll
            for (int j = 0; j < 2; j++) {
                size_t ga = (size_t)(m0 + rowA[j]) * K + k0 + qA[j] * 8;
                size_t gb = (size_t)(n0 + rowA[j]) * K + k0 + qA[j] * 8;
                pAh[j] = *(const uint4*)&Ah[ga];
                pAl[j] = *(const uint4*)&Al[ga];
                pBh[j] = *(const uint4*)&Bh[gb];
                pBl[j] = *(const uint4*)&Bl[gb];
            }
        }

#pragma unroll
        for (int ks = 0; ks < 2; ks++) {
            uint32_t aH[2][4], aL[2][4], bH[16], bL[16];
#pragma unroll
            for (int mt = 0; mt < 2; mt++) {
                uint32_t off = (uint32_t)(wm * 32 + mt * 16 + (lane & 15)) * (SROW * 2)
                               + ks * 32 + ((lane >> 4) * 16);
                ldsm4(aH[mt], uAh + off);
                ldsm4(aL[mt], uAl + off);
            }
            {
                int quarter = lane >> 3, wi = lane & 7;
#pragma unroll
                for (int p = 0; p < 4; p++) {
                    uint32_t off = (uint32_t)(wn * 64 + p * 16 + (quarter >> 1) * 8 + wi) * (SROW * 2)
                                   + ks * 32 + ((quarter & 1) * 16);
                    ldsm4(&bH[p * 4], uBh + off);
                    ldsm4(&bL[p * 4], uBl + off);
                }
            }
#pragma unroll
            for (int mt = 0; mt < 2; mt++)
#pragma unroll
                for (int nt = 0; nt < 8; nt++) {
                    mma16816(acc[mt][nt], aH[mt], &bH[nt * 2]);
                    mma16816(acc[mt][nt], aH[mt], &bL[nt * 2]);
                    mma16816(acc[mt][nt], aL[mt], &bH[nt * 2]);
                }
        }
        __syncthreads();
    }

#pragma unroll
    for (int mt = 0; mt < 2; mt++) {
        int row = m0 + wm * 32 + mt * 16 + (lane >> 2);
#pragma unroll
        for (int nt = 0; nt < 8; nt++) {
            int col = n0 + wn * 64 + nt * 8 + (lane & 3) * 2;
            float2 v0 = make_float2(acc[mt][nt][0], acc[mt][nt][1]);
            float2 v1 = make_float2(acc[mt][nt][2], acc[mt][nt][3]);
            *(float2*)&C[(size_t)row * N + col] = v0;
            *(float2*)&C[(size_t)(row + 8) * N + col] = v1;
        }
    }
}

// ---------------- RoPE tables (tiny fp64 kernel) ----------------
__global__ void rope_tables(float* __restrict__ tab) {
    int t = blockIdx.x;
    int i = threadIdx.x;
    double inv = pow(10000.0, -(double)i / 32.0);
    double f = fmod((double)t * inv, 6.283185307179586);
    float cf = (float)cos(f), sf = (float)sin(f);
    float power = ((float)t - 1024.0f) / 512.0f;
    int je = (2 * i) & 31, jo = (2 * i + 1) & 31;
    float sv_e = (2.0f * je + 25.6f) / 89.6f;
    float sv_o = (2.0f * jo + 25.6f) / 89.6f;
    float se = powf(sv_e, power), so = powf(sv_o, power);
    int idx = (t * 32 + i) * 4;
    tab[idx] = cf; tab[idx + 1] = sf; tab[idx + 2] = se; tab[idx + 3] = so;
}

// ---------------- RoPE apply: fp32 in -> split bf16 out ----------------
__global__ void rope_apply(const float* __restrict__ q, const float* __restrict__ k,
                           const float* __restrict__ tab,
                           __nv_bfloat16* __restrict__ qh, __nv_bfloat16* __restrict__ ql,
                           __nv_bfloat16* __restrict__ kh, __nv_bfloat16* __restrict__ kl) {
    int t = blockIdx.x;
    int p = threadIdx.x;
    int head = p >> 5;
    int i = p & 31;
    float4 tv = *(const float4*)&tab[(t * 32 + i) * 4];
    float cf = tv.x, sf = tv.y, se = tv.z, so = tv.w;

    size_t base = (size_t)t * E_DIM + head * 64 + 2 * i;
    float a = q[base], b = q[base + 1];
    float qa = (a * cf - b * sf) * se * 0.125f;
    float qb = (b * cf + a * sf) * so * 0.125f;
    float ka = k[base], kb = k[base + 1];
    float k0 = (ka * cf - kb * sf) / se;
    float k1 = (kb * cf + ka * sf) / so;

    __nv_bfloat162 v;
    v.x = __float2bfloat16(qa); v.y = __float2bfloat16(qb);
    *(__nv_bfloat162*)&qh[base] = v;
    __nv_bfloat162 vr;
    vr.x = __float2bfloat16(qa - __bfloat162float(v.x));
    vr.y = __float2bfloat16(qb - __bfloat162float(v.y));
    *(__nv_bfloat162*)&ql[base] = vr;
    v.x = __float2bfloat16(k0); v.y = __float2bfloat16(k1);
    *(__nv_bfloat162*)&kh[base] = v;
    vr.x = __float2bfloat16(k0 - __bfloat162float(v.x));
    vr.y = __float2bfloat16(k1 - __bfloat162float(v.y));
    *(__nv_bfloat162*)&kl[base] = vr;
}

// ---------------- lambda scalar ----------------
__global__ void lambda_kernel(const float* __restrict__ lq1, const float* __restrict__ lk1,
                              const float* __restrict__ lq2, const float* __restrict__ lk2) {
    __shared__ float s1[64], s2[64];
    int t = threadIdx.x;
    s1[t] = lq1[t] * lk1[t];
    s2[t] = lq2[t] * lk2[t];
    __syncthreads();
    if (t == 0) {
        float a = 0.f, b = 0.f;
        for (int j = 0; j < 64; j++) { a += s1[j]; b += s2[j]; }
        g_lambda = expf(a) - expf(b) + LAMBDA_INIT;
    }
}

// ---------------- HMMA differential flash attention ----------------
// 8 warps = (wm 0..3 rows, st 0..1 streams). q-block 64. Smem (bytes):
//   Qh [2st][64][72] @0, Ql @18432, Kh @36864, Kl @55296, Vh [64][136] @73728, Vl @91136
#define OQH 0
#define OQL 18432
#define OKH 36864
#define OKL 55296
#define OVH 73728
#define OVL 91136
#define ATT_SMEM 108544

__global__ __launch_bounds__(256) void diff_attn_mma(
    const __nv_bfloat16* __restrict__ qh, const __nv_bfloat16* __restrict__ ql,
    const __nv_bfloat16* __restrict__ kh, const __nv_bfloat16* __restrict__ kl,
    const __nv_bfloat16* __restrict__ vh, const __nv_bfloat16* __restrict__ vl,
    __nv_bfloat16* __restrict__ oh, __nv_bfloat16* __restrict__ ol) {
    extern __shared__ char sm[];
    const uint32_t sb = smem_u32(sm);
    const int tid = threadIdx.x;
    const int lane = tid & 31, wid = tid >> 5;
    const int wm = wid & 3, st = wid >> 2;
    const int h = blockIdx.y;
    const int q0 = blockIdx.x * 64;

    // ---- load Q (both streams, hi/lo): 2048 uint4 ----
#pragma unroll
    for (int j = 0; j < 8; j++) {
        int u = tid + j * 256;
        int arr = u >> 10, rem = u & 1023;
        int qst = rem >> 9, r2 = (rem >> 3) & 63, qq = rem & 7;
        const __nv_bfloat16* src = arr ? ql : qh;
        uint32_t off = (arr ? OQL : OQH) + (uint32_t)(qst * 64 + r2) * 144 + qq * 16;
        *(uint4*)(sm + off) =
            *(const uint4*)&src[(size_t)(q0 + r2) * E_DIM + (2 * h + qst) * 64 + qq * 8];
    }

    float O[16][4];
#pragma unroll
    for (int ct = 0; ct < 16; ct++)
#pragma unroll
        for (int i = 0; i < 4; i++) O[ct][i] = 0.f;
    float m0 = -INFINITY, m1 = -INFINITY, l0 = 0.f, l1 = 0.f;

    const int quarter = lane >> 3, wi = lane & 7;
    const uint32_t aoff_base = (uint32_t)(st * 64 + wm * 16 + (lane & 15)) * 144 + ((lane >> 4) * 16);
    const uint32_t voff_base = (uint32_t)((lane & 7) + ((lane & 8) ? 8 : 0)) * 272 + ((lane & 16) ? 16 : 0);

    for (int sbk = 0; sbk < 32; sbk++) {
        const int s0 = sbk * 64;
        __syncthreads();   // previous iteration's PV reads done before overwrite
        // ---- load K (2048 uint4) + V (2048 uint4) ----
#pragma unroll
        for (int j = 0; j < 8; j++) {
            int u = tid + j * 256;
            int arr = u >> 10, rem = u & 1023;
            int kst = rem >> 9, r2 = (rem >> 3) & 63, qq = rem & 7;
            const __nv_bfloat16* src = arr ? kl : kh;
            uint32_t off = (arr ? OKL : OKH) + (uint32_t)(kst * 64 + r2) * 144 + qq * 16;
            *(uint4*)(sm + off) =
                *(const uint4*)&src[(size_t)(s0 + r2) * E_DIM + (2 * h + kst) * 64 + qq * 8];
        }
#pragma unroll
        for (int j = 0; j < 8; j++) {
            int u = tid + j * 256;
            int arr = u >> 10, rem = u & 1023;
            int r2 = rem >> 4, qq = rem & 15;
            const __nv_bfloat16* src = arr ? vl : vh;
            uint32_t off = (arr ? OVL : OVH) + (uint32_t)r2 * 272 + qq * 16;
            *(uint4*)(sm + off) =
                *(const uint4*)&src[(size_t)(s0 + r2) * E_DIM + h * 128 + qq * 8];
        }
        __syncthreads();

        // ---- S = Q_st * K_st^T (3-term split) ----
        float sacc[8][4];
#pragma unroll
        for (int t = 0; t < 8; t++)
#pragma unroll
            for (int i = 0; i < 4; i++) sacc[t][i] = 0.f;

#pragma unroll
        for (int ks = 0; ks < 4; ks++) {
            uint32_t aQh[4], aQl[4];
            uint32_t ao = aoff_base + ks * 32;
            ldsm4(aQh, sb + OQH + ao);
            ldsm4(aQl, sb + OQL + ao);
#pragma unroll
            for (int p = 0; p < 4; p++) {
                uint32_t bo = (uint32_t)(st * 64 + p * 16 + (quarter >> 1) * 8 + wi) * 144
                              + ks * 32 + ((quarter & 1) * 16);
                uint32_t bh[4], bl[4];
                ldsm4(bh, sb + OKH + bo);
                ldsm4(bl, sb + OKL + bo);
                mma16816(sacc[2 * p], aQh, &bh[0]);
                mma16816(sacc[2 * p + 1], aQh, &bh[2]);
                mma16816(sacc[2 * p], aQh, &bl[0]);
                mma16816(sacc[2 * p + 1], aQh, &bl[2]);
                mma16816(sacc[2 * p], aQl, &bh[0]);
                mma16816(sacc[2 * p + 1], aQl, &bh[2]);
            }
        }

        // ---- online softmax (rows r=lane>>2 and r+8) ----
        float mx0 = -INFINITY, mx1 = -INFINITY;
#pragma unroll
        for (int t = 0; t < 8; t++) {
            mx0 = fmaxf(mx0, fmaxf(sacc[t][0], sacc[t][1]));
            mx1 = fmaxf(mx1, fmaxf(sacc[t][2], sacc[t][3]));
        }
        mx0 = fmaxf(mx0, __shfl_xor_sync(0xffffffffu, mx0, 1));
        mx0 = fmaxf(mx0, __shfl_xor_sync(0xffffffffu, mx0, 2));
        mx1 = fmaxf(mx1, __shfl_xor_sync(0xffffffffu, mx1, 1));
        mx1 = fmaxf(mx1, __shfl_xor_sync(0xffffffffu, mx1, 2));
        float mn0 = fmaxf(m0, mx0), mn1 = fmaxf(m1, mx1);
        float al0 = __expf(m0 - mn0), al1 = __expf(m1 - mn1);
        m0 = mn0; m1 = mn1;

        uint32_t aPh[4][4], aPl[4][4];
        float rs0 = 0.f, rs1 = 0.f;
#pragma unroll
        for (int t = 0; t < 8; t++) {
            float p0 = __expf(sacc[t][0] - mn0);
            float p1 = __expf(sacc[t][1] - mn0);
            float p2 = __expf(sacc[t][2] - mn1);
            float p3 = __expf(sacc[t][3] - mn1);
            rs0 += p0 + p1; rs1 += p2 + p3;
            int j = t >> 1, hf = t & 1;
            __nv_bfloat162 hv, lv;
            hv.x = __float2bfloat16(p0); hv.y = __float2bfloat16(p1);
            lv.x = __float2bfloat16(p0 - __bfloat162float(hv.x));
            lv.y = __float2bfloat16(p1 - __bfloat162float(hv.y));
            aPh[j][hf * 2] = *(uint32_t*)&hv;
            aPl[j][hf * 2] = *(uint32_t*)&lv;
            hv.x = __float2bfloat16(p2); hv.y = __float2bfloat16(p3);
            lv.x = __float2bfloat16(p2 - __bfloat162float(hv.x));
            lv.y = __float2bfloat16(p3 - __bfloat162float(hv.y));
            aPh[j][hf * 2 + 1] = *(uint32_t*)&hv;
            aPl[j][hf * 2 + 1] = *(uint32_t*)&lv;
        }
        rs0 += __shfl_xor_sync(0xffffffffu, rs0, 1);
        rs0 += __shfl_xor_sync(0xffffffffu, rs0, 2);
        rs1 += __shfl_xor_sync(0xffffffffu, rs1, 1);
        rs1 += __shfl_xor_sync(0xffffffffu, rs1, 2);
        l0 = l0 * al0 + rs0;
        l1 = l1 * al1 + rs1;
#pragma unroll
        for (int ct = 0; ct < 16; ct++) {
            O[ct][0] *= al0; O[ct][1] *= al0;
            O[ct][2] *= al1; O[ct][3] *= al1;
        }

        // ---- O += P * V (3-term split), B frags via ldmatrix.trans ----
#pragma unroll
        for (int p8 = 0; p8 < 8; p8++) {
#pragma unroll
            for (int j = 0; j < 4; j++) {
                uint32_t vo = voff_base + (uint32_t)(j * 16) * 272 + p8 * 32;
                uint32_t bh[4], bl[4];
                ldsm4t(bh, sb + OVH + vo);
                ldsm4t(bl, sb + OVL + vo);
                mma16816(O[2 * p8], aPh[j], &bh[0]);
                mma16816(O[2 * p8 + 1], aPh[j], &bh[2]);
                mma16816(O[2 * p8], aPh[j], &bl[0]);
                mma16816(O[2 * p8 + 1], aPh[j], &bl[2]);
                mma16816(O[2 * p8], aPl[j], &bh[0]);
                mma16816(O[2 * p8 + 1], aPl[j], &bh[2]);
            }
        }
    }

    // ---- epilogue: normalized O streams -> smem overlay -> diff + RMS -> bf16 split out ----
    __syncthreads();
    {
        float* buf = (float*)(sm + (st ? 36864 : 0));
        float inv0 = 1.0f / l0, inv1 = 1.0f / l1;
        int r = wm * 16 + (lane >> 2);
#pragma unroll
        for (int ct = 0; ct < 16; ct++) {
            int c = ct * 8 + 2 * (lane & 3);
            *(float2*)&buf[r * 128 + c] = make_float2(O[ct][0] * inv0, O[ct][1] * inv0);
            *(float2*)&buf[(r + 8) * 128 + c] = make_float2(O[ct][2] * inv1, O[ct][3] * inv1);
        }
    }
    __syncthreads();
    {
        const float lam = g_lambda;
        const float* b0 = (const float*)sm;
        const float* b1 = (const float*)(sm + 36864);
        int r = tid >> 2, qt = tid & 3;
        float vals[32];
        float ss = 0.f;
#pragma unroll
        for (int i = 0; i < 32; i++) {
            int c = qt * 32 + i;
            float d = b0[r * 128 + c] - lam * b1[r * 128 + c];
            vals[i] = d;
            ss += d * d;
        }
        ss += __shfl_xor_sync(0xffffffffu, ss, 1);
        ss += __shfl_xor_sync(0xffffffffu, ss, 2);
        float g = rsqrtf(ss * (1.0f / 128.0f) + 1e-5f) * (1.0f - LAMBDA_INIT);
        size_t base = (size_t)(q0 + r) * E_DIM + h * 128 + qt * 32;
#pragma unroll
        for (int i = 0; i < 32; i += 2) {
            float o0 = vals[i] * g, o1 = vals[i + 1] * g;
            __nv_bfloat162 hv, lv;
            hv.x = __float2bfloat16(o0); hv.y = __float2bfloat16(o1);
            lv.x = __float2bfloat16(o0 - __bfloat162float(hv.x));
            lv.y = __float2bfloat16(o1 - __bfloat162float(hv.y));
            *(__nv_bfloat162*)&oh[base + i] = hv;
            *(__nv_bfloat162*)&ol[base + i] = lv;
        }
    }
}

// ---------------- launch ----------------
extern "C" void kernel_launch(void* const* d_in, const int* in_sizes, int n_in,
                              void* d_out, int out_size) {
    const float* x   = (const float*)d_in[0];
    const float* Wq  = (const float*)d_in[1];
    const float* Wk  = (const float*)d_in[2];
    const float* Wv  = (const float*)d_in[3];
    const float* Wo  = (const float*)d_in[4];
    const float* lq1 = (const float*)d_in[5];
    const float* lk1 = (const float*)d_in[6];
    const float* lq2 = (const float*)d_in[7];
    const float* lk2 = (const float*)d_in[8];
    float* out = (float*)d_out;

    float *pq, *pk, *pv, *ptab;
    cudaGetSymbolAddress((void**)&pq, g_q);
    cudaGetSymbolAddress((void**)&pk, g_k);
    cudaGetSymbolAddress((void**)&pv, g_v);
    cudaGetSymbolAddress((void**)&ptab, g_rope);

    __nv_bfloat16 *xh, *xl, *ah, *al, *qbh, *qbl, *kbh, *kbl, *vbh, *vbl;
    __nv_bfloat16 *wqh, *wql, *wkh, *wkl, *wvh, *wvl, *woh, *wol;
    cudaGetSymbolAddress((void**)&xh, g_xh);   cudaGetSymbolAddress((void**)&xl, g_xl);
    cudaGetSymbolAddress((void**)&ah, g_ah);   cudaGetSymbolAddress((void**)&al, g_al);
    cudaGetSymbolAddress((void**)&qbh, g_qbh); cudaGetSymbolAddress((void**)&qbl, g_qbl);
    cudaGetSymbolAddress((void**)&kbh, g_kbh); cudaGetSymbolAddress((void**)&kbl, g_kbl);
    cudaGetSymbolAddress((void**)&vbh, g_vbh); cudaGetSymbolAddress((void**)&vbl, g_vbl);
    cudaGetSymbolAddress((void**)&wqh, g_wqh); cudaGetSymbolAddress((void**)&wql, g_wql);
    cudaGetSymbolAddress((void**)&wkh, g_wkh); cudaGetSymbolAddress((void**)&wkl, g_wkl);
    cudaGetSymbolAddress((void**)&wvh, g_wvh); cudaGetSymbolAddress((void**)&wvl, g_wvl);
    cudaGetSymbolAddress((void**)&woh, g_woh); cudaGetSymbolAddress((void**)&wol, g_wol);

    cudaFuncSetAttribute(diff_attn_mma, cudaFuncAttributeMaxDynamicSharedMemorySize, ATT_SMEM);

    const int nX = T_SEQ * E_DIM;
    const int nW = E_DIM * E_DIM;
    cvt_split<<<(nX + 255) / 256, 256>>>(x, xh, xl, nX);
    cvt_split<<<(nW + 255) / 256, 256>>>(Wq, wqh, wql, nW);
    cvt_split<<<(nW + 255) / 256, 256>>>(Wk, wkh, wkl, nW);
    cvt_split<<<(nW + 255) / 256, 256>>>(Wv, wvh, wvl, nW);
    cvt_split<<<(nW + 255) / 256, 256>>>(Wo, woh, wol, nW);

    rope_tables<<<T_SEQ, 32>>>(ptab);
    lambda_kernel<<<1, 64>>>(lq1, lk1, lq2, lk2);

    dim3 tgrid(E_DIM / 128, T_SEQ / 128);
    gemm_hmma<<<tgrid, 256>>>(xh, xl, wqh, wql, pq, T_SEQ, E_DIM, E_DIM);
    gemm_hmma<<<tgrid, 256>>>(xh, xl, wkh, wkl, pk, T_SEQ, E_DIM, E_DIM);
    gemm_hmma<<<tgrid, 256>>>(xh, xl, wvh, wvl, pv, T_SEQ, E_DIM, E_DIM);

    rope_apply<<<T_SEQ, 512>>>(pq, pk, ptab, qbh, qbl, kbh, kbl);
    cvt_split<<<(nX + 255) / 256, 256>>>(pv, vbh, vbl, nX);

    diff_attn_mma<<<dim3(T_SEQ / 64, NH), 256, ATT_SMEM>>>(qbh, qbl, kbh, kbl, vbh, vbl, ah, al);

    gemm_hmma<<<tgrid, 256>>>(ah, al, woh, wol, out, T_SEQ, E_DIM, E_DIM);
}

// round 12
// speedup vs baseline: 3.9833x; 1.0490x over previous
#include <cuda_runtime.h>
#include <cuda_bf16.h>
#include <cstdint>
#include <math.h>

#define T_SEQ 2048
#define E_DIM 1024
#define NH 8
#define LAMBDA_INIT 0.35550906759096927f

// ---------------- scratch (device globals; no runtime allocation) ----------------
__device__ float g_q[T_SEQ * E_DIM];
__device__ float g_k[T_SEQ * E_DIM];
__device__ float g_v[T_SEQ * E_DIM];
__device__ float g_lambda;
__device__ float g_rope[T_SEQ * 32 * 4];

__device__ __nv_bfloat16 g_xh[T_SEQ * E_DIM], g_xl[T_SEQ * E_DIM];
__device__ __nv_bfloat16 g_ah[T_SEQ * E_DIM], g_al[T_SEQ * E_DIM];
__device__ __nv_bfloat16 g_qbh[T_SEQ * E_DIM], g_qbl[T_SEQ * E_DIM];
__device__ __nv_bfloat16 g_kbh[T_SEQ * E_DIM], g_kbl[T_SEQ * E_DIM];
__device__ __nv_bfloat16 g_vbh[T_SEQ * E_DIM], g_vbl[T_SEQ * E_DIM];
__device__ __nv_bfloat16 g_wqh[E_DIM * E_DIM], g_wql[E_DIM * E_DIM];
__device__ __nv_bfloat16 g_wkh[E_DIM * E_DIM], g_wkl[E_DIM * E_DIM];
__device__ __nv_bfloat16 g_wvh[E_DIM * E_DIM], g_wvl[E_DIM * E_DIM];
__device__ __nv_bfloat16 g_woh[E_DIM * E_DIM], g_wol[E_DIM * E_DIM];

// ---------------- warp-MMA helpers (baseline PTX, works at sm_103 non-a) ----------------
__device__ __forceinline__ uint32_t smem_u32(const void* p) {
    uint32_t a;
    asm("{ .reg .u64 t; cvta.to.shared.u64 t, %1; cvt.u32.u64 %0, t; }" : "=r"(a) : "l"(p));
    return a;
}
__device__ __forceinline__ void ldsm4(uint32_t* r, uint32_t addr) {
    asm volatile("ldmatrix.sync.aligned.m8n8.x4.shared.b16 {%0,%1,%2,%3}, [%4];"
                 : "=r"(r[0]), "=r"(r[1]), "=r"(r[2]), "=r"(r[3]) : "r"(addr));
}
__device__ __forceinline__ void ldsm4t(uint32_t* r, uint32_t addr) {
    asm volatile("ldmatrix.sync.aligned.m8n8.x4.trans.shared.b16 {%0,%1,%2,%3}, [%4];"
                 : "=r"(r[0]), "=r"(r[1]), "=r"(r[2]), "=r"(r[3]) : "r"(addr));
}
__device__ __forceinline__ void mma16816(float* d, const uint32_t* a, const uint32_t* b) {
    asm volatile("mma.sync.aligned.m16n8k16.row.col.f32.bf16.bf16.f32 "
                 "{%0,%1,%2,%3}, {%4,%5,%6,%7}, {%8,%9}, {%0,%1,%2,%3};"
                 : "+f"(d[0]), "+f"(d[1]), "+f"(d[2]), "+f"(d[3])
                 : "r"(a[0]), "r"(a[1]), "r"(a[2]), "r"(a[3]), "r"(b[0]), "r"(b[1]));
}
__device__ __forceinline__ void cpa16(uint32_t s, const void* g) {
    asm volatile("cp.async.ca.shared.global [%0], [%1], 16;" :: "r"(s), "l"(g));
}
#define CPA_COMMIT() asm volatile("cp.async.commit_group;" ::: "memory")
#define CPA_WAIT(n)  asm volatile("cp.async.wait_group %0;" :: "n"(n) : "memory")

// ---------------- split-bf16 conversion ----------------
__global__ void cvt_split(const float* __restrict__ in, __nv_bfloat16* __restrict__ hi,
                          __nv_bfloat16* __restrict__ lo, int n) {
    int i = blockIdx.x * 256 + threadIdx.x;
    if (i < n) {
        float v = in[i];
        __nv_bfloat16 h = __float2bfloat16(v);
        hi[i] = h;
        lo[i] = __float2bfloat16(v - __bfloat162float(h));
    }
}

// fused cvt for 4 weight matrices (blockIdx.y selects)
__global__ void cvt_weights(const float* __restrict__ Wq, const float* __restrict__ Wk,
                            const float* __restrict__ Wv, const float* __restrict__ Wo,
                            __nv_bfloat16* __restrict__ qh, __nv_bfloat16* __restrict__ ql,
                            __nv_bfloat16* __restrict__ kh, __nv_bfloat16* __restrict__ kl,
                            __nv_bfloat16* __restrict__ vh, __nv_bfloat16* __restrict__ vl,
                            __nv_bfloat16* __restrict__ oh, __nv_bfloat16* __restrict__ ol) {
    int i = blockIdx.x * 256 + threadIdx.x;
    int w = blockIdx.y;
    const float* src = (w == 0) ? Wq : (w == 1) ? Wk : (w == 2) ? Wv : Wo;
    __nv_bfloat16* hi = (w == 0) ? qh : (w == 1) ? kh : (w == 2) ? vh : oh;
    __nv_bfloat16* lo = (w == 0) ? ql : (w == 1) ? kl : (w == 2) ? vl : ol;
    float v = src[i];
    __nv_bfloat16 h = __float2bfloat16(v);
    hi[i] = h;
    lo[i] = __float2bfloat16(v - __bfloat162float(h));
}

// ---------------- HMMA GEMM (cp.async double-buffered): C = A * B^T ----------------
// CTA 128x128, 8 warps (4M x 2N), K-chunk 32. blockIdx.z selects (B, C) set.
// dyn smem: 2 bufs x 4 arrays x 128x40 bf16 = 81920 B
#define GSROW 40
#define GARR 10240            /* bytes per array */
#define GBUFB 40960           /* bytes per buffer (4 arrays) */
#define GEMM_SMEM 81920

__global__ __launch_bounds__(256) void gemm_hmma(
    const __nv_bfloat16* __restrict__ Ah, const __nv_bfloat16* __restrict__ Al,
    const __nv_bfloat16* __restrict__ B0h, const __nv_bfloat16* __restrict__ B0l,
    const __nv_bfloat16* __restrict__ B1h, const __nv_bfloat16* __restrict__ B1l,
    const __nv_bfloat16* __restrict__ B2h, const __nv_bfloat16* __restrict__ B2l,
    float* __restrict__ C0, float* __restrict__ C1, float* __restrict__ C2,
    int M, int N, int K) {
    extern __shared__ char dsm[];
    const uint32_t sb = smem_u32(dsm);

    const int tid = threadIdx.x;
    const int lane = tid & 31, wid = tid >> 5;
    const int wm = wid & 3, wn = wid >> 2;
    const int m0 = blockIdx.y * 128, n0 = blockIdx.x * 128;
    const int z = blockIdx.z;
    const __nv_bfloat16* Bh = (z == 0) ? B0h : (z == 1) ? B1h : B2h;
    const __nv_bfloat16* Bl = (z == 0) ? B0l : (z == 1) ? B1l : B2l;
    float* C = (z == 0) ? C0 : (z == 1) ? C1 : C2;

    float acc[2][8][4];
#pragma unroll
    for (int mt = 0; mt < 2; mt++)
#pragma unroll
        for (int nt = 0; nt < 8; nt++)
#pragma unroll
            for (int i = 0; i < 4; i++) acc[mt][nt][i] = 0.f;

    int rowA[2], qA[2];
#pragma unroll
    for (int j = 0; j < 2; j++) {
        int u = tid + j * 256;
        rowA[j] = u >> 2;
        qA[j] = u & 3;
    }

    const int nchunk = K >> 5;

    // async load of chunk c into buffer b
    auto load_chunk = [&](int c, int b) {
        int k0 = c << 5;
        uint32_t bs = sb + b * GBUFB;
#pragma unroll
        for (int j = 0; j < 2; j++) {
            uint32_t so = (uint32_t)(rowA[j] * GSROW + qA[j] * 8) * 2;
            size_t ga = (size_t)(m0 + rowA[j]) * K + k0 + qA[j] * 8;
            size_t gb = (size_t)(n0 + rowA[j]) * K + k0 + qA[j] * 8;
            cpa16(bs + so, &Ah[ga]);
            cpa16(bs + GARR + so, &Al[ga]);
            cpa16(bs + 2 * GARR + so, &Bh[gb]);
            cpa16(bs + 3 * GARR + so, &Bl[gb]);
        }
        CPA_COMMIT();
    };

    load_chunk(0, 0);
    load_chunk(1, 1);

    for (int c = 0; c < nchunk; c++) {
        const int buf = c & 1;
        if (c + 1 < nchunk) CPA_WAIT(1); else CPA_WAIT(0);
        __syncthreads();

        const uint32_t uAh = sb + buf * GBUFB;
        const uint32_t uAl = uAh + GARR;
        const uint32_t uBh = uAh + 2 * GARR;
        const uint32_t uBl = uAh + 3 * GARR;

#pragma unroll
        for (int ks = 0; ks < 2; ks++) {
            uint32_t aH[2][4], aL[2][4], bH[16], bL[16];
#pragma unroll
            for (int mt = 0; mt < 2; mt++) {
                uint32_t off = (uint32_t)(wm * 32 + mt * 16 + (lane & 15)) * (GSROW * 2)
                               + ks * 32 + ((lane >> 4) * 16);
                ldsm4(aH[mt], uAh + off);
                ldsm4(aL[mt], uAl + off);
            }
            {
                int quarter = lane >> 3, wi = lane & 7;
#pragma unroll
                for (int p = 0; p < 4; p++) {
                    uint32_t off = (uint32_t)(wn * 64 + p * 16 + (quarter >> 1) * 8 + wi) * (GSROW * 2)
                                   + ks * 32 + ((quarter & 1) * 16);
                    ldsm4(&bH[p * 4], uBh + off);
                    ldsm4(&bL[p * 4], uBl + off);
                }
            }
#pragma unroll
            for (int mt = 0; mt < 2; mt++)
#pragma unroll
                for (int nt = 0; nt < 8; nt++) {
                    mma16816(acc[mt][nt], aH[mt], &bH[nt * 2]);
                    mma16816(acc[mt][nt], aH[mt], &bL[nt * 2]);
                    mma16816(acc[mt][nt], aL[mt], &bH[nt * 2]);
                }
        }
        __syncthreads();
        if (c + 2 < nchunk) load_chunk(c + 2, buf);
    }

#pragma unroll
    for (int mt = 0; mt < 2; mt++) {
        int row = m0 + wm * 32 + mt * 16 + (lane >> 2);
#pragma unroll
        for (int nt = 0; nt < 8; nt++) {
            int col = n0 + wn * 64 + nt * 8 + (lane & 3) * 2;
            float2 v0 = make_float2(acc[mt][nt][0], acc[mt][nt][1]);
            float2 v1 = make_float2(acc[mt][nt][2], acc[mt][nt][3]);
            *(float2*)&C[(size_t)row * N + col] = v0;
            *(float2*)&C[(size_t)(row + 8) * N + col] = v1;
        }
    }
}

// ---------------- RoPE tables (tiny fp64 kernel) ----------------
__global__ void rope_tables(float* __restrict__ tab) {
    int t = blockIdx.x;
    int i = threadIdx.x;
    double inv = pow(10000.0, -(double)i / 32.0);
    double f = fmod((double)t * inv, 6.283185307179586);
    float cf = (float)cos(f), sf = (float)sin(f);
    float power = ((float)t - 1024.0f) / 512.0f;
    int je = (2 * i) & 31, jo = (2 * i + 1) & 31;
    float sv_e = (2.0f * je + 25.6f) / 89.6f;
    float sv_o = (2.0f * jo + 25.6f) / 89.6f;
    float se = powf(sv_e, power), so = powf(sv_o, power);
    int idx = (t * 32 + i) * 4;
    tab[idx] = cf; tab[idx + 1] = sf; tab[idx + 2] = se; tab[idx + 3] = so;
}

// ---------------- RoPE apply: fp32 in -> split bf16 out ----------------
__global__ void rope_apply(const float* __restrict__ q, const float* __restrict__ k,
                           const float* __restrict__ tab,
                           __nv_bfloat16* __restrict__ qh, __nv_bfloat16* __restrict__ ql,
                           __nv_bfloat16* __restrict__ kh, __nv_bfloat16* __restrict__ kl) {
    int t = blockIdx.x;
    int p = threadIdx.x;
    int head = p >> 5;
    int i = p & 31;
    float4 tv = *(const float4*)&tab[(t * 32 + i) * 4];
    float cf = tv.x, sf = tv.y, se = tv.z, so = tv.w;

    size_t base = (size_t)t * E_DIM + head * 64 + 2 * i;
    float a = q[base], b = q[base + 1];
    float qa = (a * cf - b * sf) * se * 0.125f;
    float qb = (b * cf + a * sf) * so * 0.125f;
    float ka = k[base], kb = k[base + 1];
    float k0 = (ka * cf - kb * sf) / se;
    float k1 = (kb * cf + ka * sf) / so;

    __nv_bfloat162 v;
    v.x = __float2bfloat16(qa); v.y = __float2bfloat16(qb);
    *(__nv_bfloat162*)&qh[base] = v;
    __nv_bfloat162 vr;
    vr.x = __float2bfloat16(qa - __bfloat162float(v.x));
    vr.y = __float2bfloat16(qb - __bfloat162float(v.y));
    *(__nv_bfloat162*)&ql[base] = vr;
    v.x = __float2bfloat16(k0); v.y = __float2bfloat16(k1);
    *(__nv_bfloat162*)&kh[base] = v;
    vr.x = __float2bfloat16(k0 - __bfloat162float(v.x));
    vr.y = __float2bfloat16(k1 - __bfloat162float(v.y));
    *(__nv_bfloat162*)&kl[base] = vr;
}

// ---------------- lambda scalar ----------------
__global__ void lambda_kernel(const float* __restrict__ lq1, const float* __restrict__ lk1,
                              const float* __restrict__ lq2, const float* __restrict__ lk2) {
    __shared__ float s1[64], s2[64];
    int t = threadIdx.x;
    s1[t] = lq1[t] * lk1[t];
    s2[t] = lq2[t] * lk2[t];
    __syncthreads();
    if (t == 0) {
        float a = 0.f, b = 0.f;
        for (int j = 0; j < 64; j++) { a += s1[j]; b += s2[j]; }
        g_lambda = expf(a) - expf(b) + LAMBDA_INIT;
    }
}

// ---------------- HMMA differential flash attention (unchanged from R11) ----------------
#define OQH 0
#define OQL 18432
#define OKH 36864
#define OKL 55296
#define OVH 73728
#define OVL 91136
#define ATT_SMEM 108544

__global__ __launch_bounds__(256) void diff_attn_mma(
    const __nv_bfloat16* __restrict__ qh, const __nv_bfloat16* __restrict__ ql,
    const __nv_bfloat16* __restrict__ kh, const __nv_bfloat16* __restrict__ kl,
    const __nv_bfloat16* __restrict__ vh, const __nv_bfloat16* __restrict__ vl,
    __nv_bfloat16* __restrict__ oh, __nv_bfloat16* __restrict__ ol) {
    extern __shared__ char sm[];
    const uint32_t sb = smem_u32(sm);
    const int tid = threadIdx.x;
    const int lane = tid & 31, wid = tid >> 5;
    const int wm = wid & 3, st = wid >> 2;
    const int h = blockIdx.y;
    const int q0 = blockIdx.x * 64;

#pragma unroll
    for (int j = 0; j < 8; j++) {
        int u = tid + j * 256;
        int arr = u >> 10, rem = u & 1023;
        int qst = rem >> 9, r2 = (rem >> 3) & 63, qq = rem & 7;
        const __nv_bfloat16* src = arr ? ql : qh;
        uint32_t off = (arr ? OQL : OQH) + (uint32_t)(qst * 64 + r2) * 144 + qq * 16;
        *(uint4*)(sm + off) =
            *(const uint4*)&src[(size_t)(q0 + r2) * E_DIM + (2 * h + qst) * 64 + qq * 8];
    }

    float O[16][4];
#pragma unroll
    for (int ct = 0; ct < 16; ct++)
#pragma unroll
        for (int i = 0; i < 4; i++) O[ct][i] = 0.f;
    float m0 = -INFINITY, m1 = -INFINITY, l0 = 0.f, l1 = 0.f;

    const int quarter = lane >> 3, wi = lane & 7;
    const uint32_t aoff_base = (uint32_t)(st * 64 + wm * 16 + (lane & 15)) * 144 + ((lane >> 4) * 16);
    const uint32_t voff_base = (uint32_t)((lane & 7) + ((lane & 8) ? 8 : 0)) * 272 + ((lane & 16) ? 16 : 0);

    for (int sbk = 0; sbk < 32; sbk++) {
        const int s0 = sbk * 64;
        __syncthreads();
#pragma unroll
        for (int j = 0; j < 8; j++) {
            int u = tid + j * 256;
            int arr = u >> 10, rem = u & 1023;
            int kst = rem >> 9, r2 = (rem >> 3) & 63, qq = rem & 7;
            const __nv_bfloat16* src = arr ? kl : kh;
            uint32_t off = (arr ? OKL : OKH) + (uint32_t)(kst * 64 + r2) * 144 + qq * 16;
            *(uint4*)(sm + off) =
                *(const uint4*)&src[(size_t)(s0 + r2) * E_DIM + (2 * h + kst) * 64 + qq * 8];
        }
#pragma unroll
        for (int j = 0; j < 8; j++) {
            int u = tid + j * 256;
            int arr = u >> 10, rem = u & 1023;
            int r2 = rem >> 4, qq = rem & 15;
            const __nv_bfloat16* src = arr ? vl : vh;
            uint32_t off = (arr ? OVL : OVH) + (uint32_t)r2 * 272 + qq * 16;
            *(uint4*)(sm + off) =
                *(const uint4*)&src[(size_t)(s0 + r2) * E_DIM + h * 128 + qq * 8];
        }
        __syncthreads();

        float sacc[8][4];
#pragma unroll
        for (int t = 0; t < 8; t++)
#pragma unroll
            for (int i = 0; i < 4; i++) sacc[t][i] = 0.f;

#pragma unroll
        for (int ks = 0; ks < 4; ks++) {
            uint32_t aQh[4], aQl[4];
            uint32_t ao = aoff_base + ks * 32;
            ldsm4(aQh, sb + OQH + ao);
            ldsm4(aQl, sb + OQL + ao);
#pragma unroll
            for (int p = 0; p < 4; p++) {
                uint32_t bo = (uint32_t)(st * 64 + p * 16 + (quarter >> 1) * 8 + wi) * 144
                              + ks * 32 + ((quarter & 1) * 16);
                uint32_t bh[4], bl[4];
                ldsm4(bh, sb + OKH + bo);
                ldsm4(bl, sb + OKL + bo);
                mma16816(sacc[2 * p], aQh, &bh[0]);
                mma16816(sacc[2 * p + 1], aQh, &bh[2]);
                mma16816(sacc[2 * p], aQh, &bl[0]);
                mma16816(sacc[2 * p + 1], aQh, &bl[2]);
                mma16816(sacc[2 * p], aQl, &bh[0]);
                mma16816(sacc[2 * p + 1], aQl, &bh[2]);
            }
        }

        float mx0 = -INFINITY, mx1 = -INFINITY;
#pragma unroll
        for (int t = 0; t < 8; t++) {
            mx0 = fmaxf(mx0, fmaxf(sacc[t][0], sacc[t][1]));
            mx1 = fmaxf(mx1, fmaxf(sacc[t][2], sacc[t][3]));
        }
        mx0 = fmaxf(mx0, __shfl_xor_sync(0xffffffffu, mx0, 1));
        mx0 = fmaxf(mx0, __shfl_xor_sync(0xffffffffu, mx0, 2));
        mx1 = fmaxf(mx1, __shfl_xor_sync(0xffffffffu, mx1, 1));
        mx1 = fmaxf(mx1, __shfl_xor_sync(0xffffffffu, mx1, 2));
        float mn0 = fmaxf(m0, mx0), mn1 = fmaxf(m1, mx1);
        float al0 = __expf(m0 - mn0), al1 = __expf(m1 - mn1);
        m0 = mn0; m1 = mn1;

        uint32_t aPh[4][4], aPl[4][4];
        float rs0 = 0.f, rs1 = 0.f;
#pragma unroll
        for (int t = 0; t < 8; t++) {
            float p0 = __expf(sacc[t][0] - mn0);
            float p1 = __expf(sacc[t][1] - mn0);
            float p2 = __expf(sacc[t][2] - mn1);
            float p3 = __expf(sacc[t][3] - mn1);
            rs0 += p0 + p1; rs1 += p2 + p3;
            int j = t >> 1, hf = t & 1;
            __nv_bfloat162 hv, lv;
            hv.x = __float2bfloat16(p0); hv.y = __float2bfloat16(p1);
            lv.x = __float2bfloat16(p0 - __bfloat162float(hv.x));
            lv.y = __float2bfloat16(p1 - __bfloat162float(hv.y));
            aPh[j][hf * 2] = *(uint32_t*)&hv;
            aPl[j][hf * 2] = *(uint32_t*)&lv;
            hv.x = __float2bfloat16(p2); hv.y = __float2bfloat16(p3);
            lv.x = __float2bfloat16(p2 - __bfloat162float(hv.x));
            lv.y = __float2bfloat16(p3 - __bfloat162float(hv.y));
            aPh[j][hf * 2 + 1] = *(uint32_t*)&hv;
            aPl[j][hf * 2 + 1] = *(uint32_t*)&lv;
        }
        rs0 += __shfl_xor_sync(0xffffffffu, rs0, 1);
        rs0 += __shfl_xor_sync(0xffffffffu, rs0, 2);
        rs1 += __shfl_xor_sync(0xffffffffu, rs1, 1);
        rs1 += __shfl_xor_sync(0xffffffffu, rs1, 2);
        l0 = l0 * al0 + rs0;
        l1 = l1 * al1 + rs1;
#pragma unroll
        for (int ct = 0; ct < 16; ct++) {
            O[ct][0] *= al0; O[ct][1] *= al0;
            O[ct][2] *= al1; O[ct][3] *= al1;
        }

#pragma unroll
        for (int p8 = 0; p8 < 8; p8++) {
#pragma unroll
            for (int j = 0; j < 4; j++) {
                uint32_t vo = voff_base + (uint32_t)(j * 16) * 272 + p8 * 32;
                uint32_t bh[4], bl[4];
                ldsm4t(bh, sb + OVH + vo);
                ldsm4t(bl, sb + OVL + vo);
                mma16816(O[2 * p8], aPh[j], &bh[0]);
                mma16816(O[2 * p8 + 1], aPh[j], &bh[2]);
                mma16816(O[2 * p8], aPh[j], &bl[0]);
                mma16816(O[2 * p8 + 1], aPh[j], &bl[2]);
                mma16816(O[2 * p8], aPl[j], &bh[0]);
                mma16816(O[2 * p8 + 1], aPl[j], &bh[2]);
            }
        }
    }

    __syncthreads();
    {
        float* buf = (float*)(sm + (st ? 36864 : 0));
        float inv0 = 1.0f / l0, inv1 = 1.0f / l1;
        int r = wm * 16 + (lane >> 2);
#pragma unroll
        for (int ct = 0; ct < 16; ct++) {
            int c = ct * 8 + 2 * (lane & 3);
            *(float2*)&buf[r * 128 + c] = make_float2(O[ct][0] * inv0, O[ct][1] * inv0);
            *(float2*)&buf[(r + 8) * 128 + c] = make_float2(O[ct][2] * inv1, O[ct][3] * inv1);
        }
    }
    __syncthreads();
    {
        const float lam = g_lambda;
        const float* b0 = (const float*)sm;
        const float* b1 = (const float*)(sm + 36864);
        int r = tid >> 2, qt = tid & 3;
        float vals[32];
        float ss = 0.f;
#pragma unroll
        for (int i = 0; i < 32; i++) {
            int c = qt * 32 + i;
            float d = b0[r * 128 + c] - lam * b1[r * 128 + c];
            vals[i] = d;
            ss += d * d;
        }
        ss += __shfl_xor_sync(0xffffffffu, ss, 1);
        ss += __shfl_xor_sync(0xffffffffu, ss, 2);
        float g = rsqrtf(ss * (1.0f / 128.0f) + 1e-5f) * (1.0f - LAMBDA_INIT);
        size_t base = (size_t)(q0 + r) * E_DIM + h * 128 + qt * 32;
#pragma unroll
        for (int i = 0; i < 32; i += 2) {
            float o0 = vals[i] * g, o1 = vals[i + 1] * g;
            __nv_bfloat162 hv, lv;
            hv.x = __float2bfloat16(o0); hv.y = __float2bfloat16(o1);
            lv.x = __float2bfloat16(o0 - __bfloat162float(hv.x));
            lv.y = __float2bfloat16(o1 - __bfloat162float(hv.y));
            *(__nv_bfloat162*)&oh[base + i] = hv;
            *(__nv_bfloat162*)&ol[base + i] = lv;
        }
    }
}

// ---------------- launch ----------------
extern "C" void kernel_launch(void* const* d_in, const int* in_sizes, int n_in,
                              void* d_out, int out_size) {
    const float* x   = (const float*)d_in[0];
    const float* Wq  = (const float*)d_in[1];
    const float* Wk  = (const float*)d_in[2];
    const float* Wv  = (const float*)d_in[3];
    const float* Wo  = (const float*)d_in[4];
    const float* lq1 = (const float*)d_in[5];
    const float* lk1 = (const float*)d_in[6];
    const float* lq2 = (const float*)d_in[7];
    const float* lk2 = (const float*)d_in[8];
    float* out = (float*)d_out;

    float *pq, *pk, *pv, *ptab;
    cudaGetSymbolAddress((void**)&pq, g_q);
    cudaGetSymbolAddress((void**)&pk, g_k);
    cudaGetSymbolAddress((void**)&pv, g_v);
    cudaGetSymbolAddress((void**)&ptab, g_rope);

    __nv_bfloat16 *xh, *xl, *ah, *al, *qbh, *qbl, *kbh, *kbl, *vbh, *vbl;
    __nv_bfloat16 *wqh, *wql, *wkh, *wkl, *wvh, *wvl, *woh, *wol;
    cudaGetSymbolAddress((void**)&xh, g_xh);   cudaGetSymbolAddress((void**)&xl, g_xl);
    cudaGetSymbolAddress((void**)&ah, g_ah);   cudaGetSymbolAddress((void**)&al, g_al);
    cudaGetSymbolAddress((void**)&qbh, g_qbh); cudaGetSymbolAddress((void**)&qbl, g_qbl);
    cudaGetSymbolAddress((void**)&kbh, g_kbh); cudaGetSymbolAddress((void**)&kbl, g_kbl);
    cudaGetSymbolAddress((void**)&vbh, g_vbh); cudaGetSymbolAddress((void**)&vbl, g_vbl);
    cudaGetSymbolAddress((void**)&wqh, g_wqh); cudaGetSymbolAddress((void**)&wql, g_wql);
    cudaGetSymbolAddress((void**)&wkh, g_wkh); cudaGetSymbolAddress((void**)&wkl, g_wkl);
    cudaGetSymbolAddress((void**)&wvh, g_wvh); cudaGetSymbolAddress((void**)&wvl, g_wvl);
    cudaGetSymbolAddress((void**)&woh, g_woh); cudaGetSymbolAddress((void**)&wol, g_wol);

    cudaFuncSetAttribute(gemm_hmma, cudaFuncAttributeMaxDynamicSharedMemorySize, GEMM_SMEM);
    cudaFuncSetAttribute(diff_attn_mma, cudaFuncAttributeMaxDynamicSharedMemorySize, ATT_SMEM);

    const int nX = T_SEQ * E_DIM;
    const int nW = E_DIM * E_DIM;
    cvt_split<<<(nX + 255) / 256, 256>>>(x, xh, xl, nX);
    cvt_weights<<<dim3(nW / 256, 4), 256>>>(Wq, Wk, Wv, Wo, wqh, wql, wkh, wkl,
                                            wvh, wvl, woh, wol);

    rope_tables<<<T_SEQ, 32>>>(ptab);
    lambda_kernel<<<1, 64>>>(lq1, lk1, lq2, lk2);

    // fused Q/K/V projections (z selects weight/output)
    gemm_hmma<<<dim3(E_DIM / 128, T_SEQ / 128, 3), 256, GEMM_SMEM>>>(
        xh, xl, wqh, wql, wkh, wkl, wvh, wvl, pq, pk, pv, T_SEQ, E_DIM, E_DIM);

    rope_apply<<<T_SEQ, 512>>>(pq, pk, ptab, qbh, qbl, kbh, kbl);
    cvt_split<<<(nX + 255) / 256, 256>>>(pv, vbh, vbl, nX);

    diff_attn_mma<<<dim3(T_SEQ / 64, NH), 256, ATT_SMEM>>>(qbh, qbl, kbh, kbl, vbh, vbl, ah, al);

    // output projection
    gemm_hmma<<<dim3(E_DIM / 128, T_SEQ / 128, 1), 256, GEMM_SMEM>>>(
        ah, al, woh, wol, woh, wol, woh, wol, out, out, out, T_SEQ, E_DIM, E_DIM);
}